// round 3
// baseline (speedup 1.0000x reference)
#include <cuda_runtime.h>
#include <cstdint>

// prediction [M=16, K=16, N=16, B=2048, C=10] fp32; label [B] int32 (JAX x64 off).
// Output: scalar fp32 = fraction of (m,k,n,b) slices where argmax_c pred == label[b].
// Single fused kernel: stream + count + last-block finalize (graph-replay safe:
// counters self-reset every run).
#define NC 10
#define NB 2048
#define N_SLICES (16 * 16 * 16 * 2048)      // 8,388,608 = 2^23
#define TPB 256
#define F2_PER_SLICE 5                       // 10 floats = 5 float2 (40 B)
#define GRID (N_SLICES / TPB)                // 32768 blocks

__device__ unsigned int g_correct_count;     // zero-init at load; reset each run
__device__ unsigned int g_blocks_done;       // zero-init at load; reset each run

__global__ __launch_bounds__(TPB) void accuracy_fused_kernel(
    const float* __restrict__ pred,
    const int* __restrict__ label,
    float* __restrict__ out)
{
    __shared__ float2 tile[TPB * F2_PER_SLICE];   // 256 slices * 40 B = 10 KB
    __shared__ unsigned int warp_sums[TPB / 32];

    const int tid = threadIdx.x;
    const long long block_slice0 = (long long)blockIdx.x * TPB;

    // Coalesced staging: this block's 256 slices = 1280 contiguous float2.
    const float2* __restrict__ src =
        reinterpret_cast<const float2*>(pred) + block_slice0 * F2_PER_SLICE;
#pragma unroll
    for (int j = 0; j < F2_PER_SLICE; j++) {
        tile[j * TPB + tid] = src[(long long)j * TPB + tid];
    }
    __syncthreads();

    // Unpack this thread's slice (10 class scores) from shared.
    float v[NC];
#pragma unroll
    for (int j = 0; j < F2_PER_SLICE; j++) {
        float2 p = tile[tid * F2_PER_SLICE + j];
        v[2 * j]     = p.x;
        v[2 * j + 1] = p.y;
    }

    // First-max argmax over 10 classes (matches jnp.argmax tie-breaking).
    float best = v[0];
    int best_idx = 0;
#pragma unroll
    for (int c = 1; c < NC; c++) {
        if (v[c] > best) { best = v[c]; best_idx = c; }
    }

    const int slice = (int)(block_slice0 + tid);
    const int b = slice & (NB - 1);
    const int correct = (best_idx == label[b]) ? 1 : 0;

    // Warp ballot -> popc -> block reduce (exact integer path).
    unsigned int bal = __ballot_sync(0xFFFFFFFFu, correct);
    const int lane = tid & 31;
    const int wid  = tid >> 5;
    if (lane == 0) warp_sums[wid] = __popc(bal);
    __syncthreads();

    if (tid == 0) {
        unsigned int s = 0;
#pragma unroll
        for (int w = 0; w < TPB / 32; w++) s += warp_sums[w];
        atomicAdd(&g_correct_count, s);
        __threadfence();
        unsigned int done = atomicAdd(&g_blocks_done, 1u);
        if (done == GRID - 1) {
            // All partials visible (each add happens-before its done-increment).
            unsigned int total = atomicAdd(&g_correct_count, 0u);  // L2 read
            out[0] = (float)total * (1.0f / (float)N_SLICES);      // exact /2^23
            // Self-reset for the next graph replay.
            g_correct_count = 0u;
            g_blocks_done = 0u;
            __threadfence();
        }
    }
}

extern "C" void kernel_launch(void* const* d_in, const int* in_sizes, int n_in,
                              void* d_out, int out_size) {
    const float* pred = (const float*)d_in[0];
    const int* label = (const int*)d_in[1];
    float* out = (float*)d_out;

    accuracy_fused_kernel<<<GRID, TPB>>>(pred, label, out);
}

// round 4
// speedup vs baseline: 1.0094x; 1.0094x over previous
#include <cuda_runtime.h>
#include <cstdint>

// prediction [16,16,16,2048,10] fp32; label [2048] int32 (JAX x64 off).
// Output scalar fp32 = fraction of slices where argmax_c pred == label[b].
#define NC 10
#define NB 2048
#define N_SLICES (16 * 16 * 16 * 2048)        // 8,388,608 = 2^23
#define TPB 256
#define CHUNK_SLICES 512                       // per staging chunk (2 slices/thread)
#define F4_PER_CHUNK (CHUNK_SLICES * NC / 4)   // 1280 float4 = 20 KB
#define CHUNKS_PER_BLOCK 8
#define GRID (N_SLICES / (CHUNK_SLICES * CHUNKS_PER_BLOCK))   // 2048 blocks

__device__ unsigned int g_correct_count;   // zero at load; self-reset each run
__device__ unsigned int g_blocks_done;

__device__ __forceinline__ int argmax10(const float* __restrict__ v) {
    float best = v[0];
    int idx = 0;
#pragma unroll
    for (int c = 1; c < NC; c++) {
        if (v[c] > best) { best = v[c]; idx = c; }
    }
    return idx;
}

__global__ __launch_bounds__(TPB) void accuracy_fused_kernel(
    const float* __restrict__ pred,
    const int* __restrict__ label,
    float* __restrict__ out)
{
    __shared__ float4 tile[F4_PER_CHUNK];      // 20 KB
    __shared__ unsigned int warp_sums[TPB / 32];

    const int tid = threadIdx.x;
    const long long chunk0 = (long long)blockIdx.x * CHUNKS_PER_BLOCK;
    unsigned int my_correct = 0;

    for (int c = 0; c < CHUNKS_PER_BLOCK; c++) {
        const long long slice0 = (chunk0 + c) * CHUNK_SLICES;
        // 512 slices * 10 floats = 1280 contiguous float4, fully coalesced LDG.128.
        const float4* __restrict__ src =
            reinterpret_cast<const float4*>(pred) + (slice0 >> 1) * 5;
#pragma unroll
        for (int j = 0; j < 5; j++) {
            tile[j * TPB + tid] = src[j * TPB + tid];
        }
        __syncthreads();

        // Thread owns slices 2*tid and 2*tid+1: float4 [5*tid, 5*tid+5).
        // LDS.128 byte stride 80/lane -> each quarter-warp phase hits all 32
        // banks exactly once: conflict-free.
        float4 q[5];
#pragma unroll
        for (int j = 0; j < 5; j++) q[j] = tile[5 * tid + j];

        float a[NC] = { q[0].x, q[0].y, q[0].z, q[0].w,
                        q[1].x, q[1].y, q[1].z, q[1].w,
                        q[2].x, q[2].y };
        float b[NC] = { q[2].z, q[2].w,
                        q[3].x, q[3].y, q[3].z, q[3].w,
                        q[4].x, q[4].y, q[4].z, q[4].w };

        const int i0 = argmax10(a);
        const int i1 = argmax10(b);

        const long long sl = slice0 + 2 * tid;
        const int b0 = (int)(sl & (NB - 1));        // slice0 % 512 == 0, 2*tid < 512
        my_correct += (i0 == label[b0]) ? 1u : 0u;
        my_correct += (i1 == label[b0 + 1]) ? 1u : 0u;

        __syncthreads();   // tile reused next chunk
    }

    // Warp redux -> block reduce -> one atomic per block (2048 total, exact).
    unsigned int warp_total = __reduce_add_sync(0xFFFFFFFFu, my_correct);
    const int lane = tid & 31;
    const int wid  = tid >> 5;
    if (lane == 0) warp_sums[wid] = warp_total;
    __syncthreads();

    if (tid == 0) {
        unsigned int s = 0;
#pragma unroll
        for (int w = 0; w < TPB / 32; w++) s += warp_sums[w];
        atomicAdd(&g_correct_count, s);
        __threadfence();
        unsigned int done = atomicAdd(&g_blocks_done, 1u);
        if (done == GRID - 1) {
            unsigned int total = atomicAdd(&g_correct_count, 0u);   // L2 read
            out[0] = (float)total * (1.0f / (float)N_SLICES);       // exact /2^23
            g_correct_count = 0u;                                   // replay-safe reset
            g_blocks_done = 0u;
            __threadfence();
        }
    }
}

extern "C" void kernel_launch(void* const* d_in, const int* in_sizes, int n_in,
                              void* d_out, int out_size) {
    const float* pred = (const float*)d_in[0];
    const int* label = (const int*)d_in[1];
    float* out = (float*)d_out;

    accuracy_fused_kernel<<<GRID, TPB>>>(pred, label, out);
}

// round 6
// speedup vs baseline: 1.0857x; 1.0756x over previous
#include <cuda_runtime.h>
#include <cstdint>

// prediction [16,16,16,2048,10] fp32; label [2048] int32 (JAX x64 off).
// Output scalar fp32 = fraction of slices where argmax_c pred == label[b].
#define NC 10
#define NB 2048
#define N_SLICES (16 * 16 * 16 * 2048)        // 8,388,608 = 2^23
#define TPB 256
#define CHUNK_SLICES 512                       // 2 slices/thread/chunk
#define F4_PER_CHUNK (CHUNK_SLICES * NC / 4)   // 1280 float4 = 20 KB
#define F4_PER_THREAD 5                        // per chunk
#define CHUNKS_PER_BLOCK 8
#define GRID (N_SLICES / (CHUNK_SLICES * CHUNKS_PER_BLOCK))   // 2048 blocks

__device__ unsigned int g_correct_count;   // zero at load; self-reset each run
__device__ unsigned int g_blocks_done;

__device__ __forceinline__ int argmax10(const float* __restrict__ v) {
    float best = v[0];
    int idx = 0;
#pragma unroll
    for (int c = 1; c < NC; c++) {
        if (v[c] > best) { best = v[c]; idx = c; }
    }
    return idx;
}

__device__ __forceinline__ void cp_async16(uint32_t smem_addr, const void* gptr) {
    asm volatile("cp.async.cg.shared.global [%0], [%1], 16;\n"
                 :: "r"(smem_addr), "l"(gptr));
}
__device__ __forceinline__ void cp_async_commit() {
    asm volatile("cp.async.commit_group;\n");
}
template <int N>
__device__ __forceinline__ void cp_async_wait() {
    asm volatile("cp.async.wait_group %0;\n" :: "n"(N));
}

__global__ __launch_bounds__(TPB) void accuracy_fused_kernel(
    const float* __restrict__ pred,
    const int* __restrict__ label,
    float* __restrict__ out)
{
    __shared__ float4 tile[2][F4_PER_CHUNK];   // 2 x 20 KB
    __shared__ unsigned int warp_sums[TPB / 32];

    const int tid = threadIdx.x;
    const long long chunk0 = (long long)blockIdx.x * CHUNKS_PER_BLOCK;
    unsigned int my_correct = 0;

    // smem byte addresses of this thread's staging slots in each buffer
    uint32_t tile_addr[2];
#pragma unroll
    for (int buf = 0; buf < 2; buf++) {
        tile_addr[buf] = (uint32_t)__cvta_generic_to_shared(&tile[buf][tid]);
    }

    // Prefetch chunk 0 into buf 0: 1280 float4, coalesced 16B cp.async (L1 bypass).
    {
        const float4* src = reinterpret_cast<const float4*>(pred)
                          + chunk0 * (CHUNK_SLICES * NC / 4 / 1) / CHUNKS_PER_BLOCK * CHUNKS_PER_BLOCK // placeholder avoided below
                          ;
        (void)src;
    }
    {
        const float4* src = reinterpret_cast<const float4*>(pred)
                          + chunk0 * F4_PER_CHUNK;
#pragma unroll
        for (int j = 0; j < F4_PER_THREAD; j++) {
            cp_async16(tile_addr[0] + (uint32_t)(j * TPB) * 16u,
                       src + j * TPB + tid);
        }
        cp_async_commit();
    }

    for (int c = 0; c < CHUNKS_PER_BLOCK; c++) {
        const int cur = c & 1;
        // Prefetch next chunk into the other buffer (it was fully consumed
        // two iterations ago; __syncthreads below guarantees safety).
        if (c + 1 < CHUNKS_PER_BLOCK) {
            const float4* src = reinterpret_cast<const float4*>(pred)
                              + (chunk0 + c + 1) * F4_PER_CHUNK;
            const uint32_t dst = tile_addr[cur ^ 1];
#pragma unroll
            for (int j = 0; j < F4_PER_THREAD; j++) {
                cp_async16(dst + (uint32_t)(j * TPB) * 16u,
                           src + j * TPB + tid);
            }
            cp_async_commit();
            cp_async_wait<1>();   // oldest group (current chunk) complete
        } else {
            cp_async_wait<0>();
        }
        __syncthreads();          // all threads' staged data visible

        // Thread owns slices 2*tid, 2*tid+1: float4 [5*tid, 5*tid+5).
        // 80 B/lane stride -> conflict-free LDS.128 phases.
        float4 q[5];
#pragma unroll
        for (int j = 0; j < 5; j++) q[j] = tile[cur][5 * tid + j];

        float a[NC] = { q[0].x, q[0].y, q[0].z, q[0].w,
                        q[1].x, q[1].y, q[1].z, q[1].w,
                        q[2].x, q[2].y };
        float b[NC] = { q[2].z, q[2].w,
                        q[3].x, q[3].y, q[3].z, q[3].w,
                        q[4].x, q[4].y, q[4].z, q[4].w };

        const int i0 = argmax10(a);
        const int i1 = argmax10(b);

        const int b0 = 2 * tid;   // CHUNK_SLICES=512 divides NB: batch idx = 2*tid mod 2048
        my_correct += (i0 == label[b0]) ? 1u : 0u;
        my_correct += (i1 == label[b0 + 1]) ? 1u : 0u;

        __syncthreads();          // reads done before buffer is overwritten
    }

    // Warp redux -> block reduce -> one atomic per block (2048 total, exact).
    unsigned int warp_total = __reduce_add_sync(0xFFFFFFFFu, my_correct);
    const int lane = tid & 31;
    const int wid  = tid >> 5;
    if (lane == 0) warp_sums[wid] = warp_total;
    __syncthreads();

    if (tid == 0) {
        unsigned int s = 0;
#pragma unroll
        for (int w = 0; w < TPB / 32; w++) s += warp_sums[w];
        atomicAdd(&g_correct_count, s);
        __threadfence();
        unsigned int done = atomicAdd(&g_blocks_done, 1u);
        if (done == GRID - 1) {
            unsigned int total = atomicAdd(&g_correct_count, 0u);   // L2 read
            out[0] = (float)total * (1.0f / (float)N_SLICES);       // exact /2^23
            g_correct_count = 0u;                                   // replay-safe
            g_blocks_done = 0u;
            __threadfence();
        }
    }
}

extern "C" void kernel_launch(void* const* d_in, const int* in_sizes, int n_in,
                              void* d_out, int out_size) {
    const float* pred = (const float*)d_in[0];
    const int* label = (const int*)d_in[1];
    float* out = (float*)d_out;

    accuracy_fused_kernel<<<GRID, TPB>>>(pred, label, out);
}

// round 7
// speedup vs baseline: 1.0942x; 1.0078x over previous
#include <cuda_runtime.h>
#include <cstdint>

// prediction [16,16,16,2048,10] fp32; label [2048] int32 (JAX x64 off).
// Output scalar fp32 = fraction of slices where argmax_c pred == label[b].
#define NC 10
#define NB 2048
#define N_SLICES (16 * 16 * 16 * 2048)        // 8,388,608 = 2^23
#define TPB 256                                // 8 warps
#define CHUNK_SLICES 512                       // per block per chunk (2/thread)
#define F4_PER_CHUNK (CHUNK_SLICES * NC / 4)   // 1280 float4 = 20 KB
#define SLICES_PER_WARP 64                     // per chunk
#define F4_PER_WARP 160                        // 64*10/4
#define F4_PER_LANE 5
#define CHUNKS_PER_BLOCK 8
#define GRID (N_SLICES / (CHUNK_SLICES * CHUNKS_PER_BLOCK))   // 2048 blocks

__device__ unsigned int g_correct_count;   // zero at load; self-reset each run
__device__ unsigned int g_blocks_done;

__device__ __forceinline__ int argmax10(const float* __restrict__ v) {
    float best = v[0];
    int idx = 0;
#pragma unroll
    for (int c = 1; c < NC; c++) {
        if (v[c] > best) { best = v[c]; idx = c; }
    }
    return idx;
}

__device__ __forceinline__ void cp_async16(uint32_t smem_addr, const void* gptr) {
    asm volatile("cp.async.cg.shared.global [%0], [%1], 16;\n"
                 :: "r"(smem_addr), "l"(gptr));
}
__device__ __forceinline__ void cp_async_commit() {
    asm volatile("cp.async.commit_group;\n");
}
template <int N>
__device__ __forceinline__ void cp_async_wait() {
    asm volatile("cp.async.wait_group %0;\n" :: "n"(N));
}

__global__ __launch_bounds__(TPB) void accuracy_fused_kernel(
    const float* __restrict__ pred,
    const int* __restrict__ label,
    float* __restrict__ out)
{
    __shared__ float4 tile[2][F4_PER_CHUNK];   // 2 x 20 KB, warp-partitioned
    __shared__ unsigned int warp_sums[TPB / 32];

    const int tid  = threadIdx.x;
    const int lane = tid & 31;
    const int wid  = tid >> 5;
    const long long chunk0 = (long long)blockIdx.x * CHUNKS_PER_BLOCK;   // mult of 8

    // This warp's staging regions (float4 index w*160 within each buffer).
    float4* const wtile0 = &tile[0][wid * F4_PER_WARP];
    float4* const wtile1 = &tile[1][wid * F4_PER_WARP];
    const uint32_t waddr0 = (uint32_t)__cvta_generic_to_shared(wtile0);
    const uint32_t waddr1 = (uint32_t)__cvta_generic_to_shared(wtile1);

    // Global base for this warp's slice stream (float4 units).
    // Chunk c covers slices (chunk0+c)*512; warp w owns slices [w*64, w*64+64).
    const float4* const gbase = reinterpret_cast<const float4*>(pred)
                              + chunk0 * F4_PER_CHUNK + wid * F4_PER_WARP;

    // Batch index of this thread's 2 slices in chunk c:
    //   (slice0 + w*64 + 2*lane) mod 2048, slice0 mod 2048 = (c&3)*512
    // (chunk0 mod 4 == 0). Preload the 4 label pairs into registers.
    int lab0[4], lab1[4];
#pragma unroll
    for (int q = 0; q < 4; q++) {
        int2 lp = *reinterpret_cast<const int2*>(
            label + (q * CHUNK_SLICES + wid * SLICES_PER_WARP + 2 * lane));
        lab0[q] = lp.x;
        lab1[q] = lp.y;
    }

    unsigned int my_correct = 0;

    // Prefetch chunk 0 into buf 0 (warp-private; 5 coalesced 16B cp.async/lane).
#pragma unroll
    for (int j = 0; j < F4_PER_LANE; j++) {
        cp_async16(waddr0 + (uint32_t)(j * 32 + lane) * 16u,
                   gbase + j * 32 + lane);
    }
    cp_async_commit();

    for (int c = 0; c < CHUNKS_PER_BLOCK; c++) {
        const int cur = c & 1;
        const uint32_t nxt_addr = cur ? waddr0 : waddr1;
        if (c + 1 < CHUNKS_PER_BLOCK) {
            const float4* src = gbase + (long long)(c + 1) * F4_PER_CHUNK;
#pragma unroll
            for (int j = 0; j < F4_PER_LANE; j++) {
                cp_async16(nxt_addr + (uint32_t)(j * 32 + lane) * 16u,
                           src + j * 32 + lane);
            }
            cp_async_commit();
            cp_async_wait<1>();   // current chunk's group complete (this lane)
        } else {
            cp_async_wait<0>();
        }
        __syncwarp();             // all lanes waited -> warp's staged data visible

        // Lane owns slices 2*lane, 2*lane+1 of the warp's 64:
        // float4 [5*lane, 5*lane+5). 80 B/lane stride -> conflict-free LDS.128.
        const float4* wt = cur ? wtile1 : wtile0;
        float4 q[5];
#pragma unroll
        for (int j = 0; j < 5; j++) q[j] = wt[5 * lane + j];

        float a[NC] = { q[0].x, q[0].y, q[0].z, q[0].w,
                        q[1].x, q[1].y, q[1].z, q[1].w,
                        q[2].x, q[2].y };
        float b[NC] = { q[2].z, q[2].w,
                        q[3].x, q[3].y, q[3].z, q[3].w,
                        q[4].x, q[4].y, q[4].z, q[4].w };

        const int i0 = argmax10(a);
        const int i1 = argmax10(b);

        const int qsel = c & 3;
        my_correct += (i0 == lab0[qsel]) ? 1u : 0u;
        my_correct += (i1 == lab1[qsel]) ? 1u : 0u;

        __syncwarp();             // reads done before this buffer is re-filled
    }

    // Warp redux -> block reduce -> one atomic per block (2048 total, exact).
    unsigned int warp_total = __reduce_add_sync(0xFFFFFFFFu, my_correct);
    if (lane == 0) warp_sums[wid] = warp_total;
    __syncthreads();

    if (tid == 0) {
        unsigned int s = 0;
#pragma unroll
        for (int w = 0; w < TPB / 32; w++) s += warp_sums[w];
        atomicAdd(&g_correct_count, s);
        __threadfence();
        unsigned int done = atomicAdd(&g_blocks_done, 1u);
        if (done == GRID - 1) {
            unsigned int total = atomicAdd(&g_correct_count, 0u);   // L2 read
            out[0] = (float)total * (1.0f / (float)N_SLICES);       // exact /2^23
            g_correct_count = 0u;                                   // replay-safe
            g_blocks_done = 0u;
            __threadfence();
        }
    }
}

extern "C" void kernel_launch(void* const* d_in, const int* in_sizes, int n_in,
                              void* d_out, int out_size) {
    const float* pred = (const float*)d_in[0];
    const int* label = (const int*)d_in[1];
    float* out = (float*)d_out;

    accuracy_fused_kernel<<<GRID, TPB>>>(pred, label, out);
}